// round 13
// baseline (speedup 1.0000x reference)
#include <cuda_runtime.h>
#include <cstdint>
#include <math.h>

// ---------------------------------------------------------------------------
// Problem constants
// ---------------------------------------------------------------------------
#define NVOX    64          // 4*4*4 voxels (batch 1)
#define K1V     11520       // N_RADII * idim(HID1) = 64 * 180
#define XOUT_N  11520       // 64 * 180  (x_out elements)
#define GRID1_N 53084160    // 64 * 11520 * 72
#define RAD_OFF (XOUT_N + GRID1_N)

#define RS64 0.125f
#define RS32 0.17677669529663687f   // 1/sqrt(32)
#define RS16 0.25f
#define RS8  0.35355339059327373f   // 1/sqrt(8)

#define VB 8
#define GX  (K1V / 64)      // 180 blocks in x
#define GY  (NVOX / VB)     // 8 blocks in y
#define NBLK (GX * GY)      // 1440

// scratch / sync (allocation-free rule: __device__ globals; zero-initialized)
__device__ __align__(16) float g_x1[NVOX * 180];   // HID1 features
__device__ unsigned g_ready = 0;                   // producer arrival count
__device__ unsigned g_done  = 0;                   // block completion count

__device__ __forceinline__ unsigned int smem_u32(const void* p) {
    unsigned int a;
    asm("{ .reg .u64 tmp; cvta.to.shared.u64 tmp, %1; cvt.u32.u64 %0, tmp; }"
        : "=r"(a) : "l"(p));
    return a;
}

__device__ __forceinline__ unsigned ld_acquire_gpu(unsigned* p) {
    unsigned v;
    asm volatile("ld.acquire.gpu.global.u32 %0, [%1];" : "=r"(v) : "l"(p) : "memory");
    return v;
}

// ---------------------------------------------------------------------------
// Single fused kernel with device-side producer barrier.
// Blocks with lin id < 64 compute x1 for one voxel (the old k_pre, NOT
// replicated), then arrive on g_ready. Everyone spins until g_ready == 64,
// then runs the R10 main loop (weights->regs, trig-immediate projection,
// double-buffered block tile, one TMA bulk store per (block, voxel)).
// Last block resets the flags so the kernel is graph-replayable.
// ---------------------------------------------------------------------------
__global__ void __launch_bounds__(64) k_all(
    const float* __restrict__ x,         // [64,120]
    const float* __restrict__ w1b0_0e,   // [32,64]
    const float* __restrict__ w1b0_1o,   // [16,16]
    const float* __restrict__ w1b0_2e,   // [8,16]
    const float* __restrict__ w1b1_0e,   // [64,32]
    const float* __restrict__ w1b1_1o,   // [16,8]
    const float* __restrict__ w1b1_2e,   // [16,8]
    const float* __restrict__ w0e,       // [32,K1]
    const float* __restrict__ w1o,       // [8,K1]
    const float* __restrict__ w2e,       // [8,K1]
    float* __restrict__ out)
{
    __shared__ __align__(16) float sx[VB * 180];
    __shared__ __align__(16) float stage[2][64 * 72];   // [buf][block tile] 36864 B

    const int t   = threadIdx.x;
    const int l   = t & 31;
    const int k   = blockIdx.x * 64 + t;
    const int v0  = blockIdx.y * VB;
    const int lin = blockIdx.y * GX + blockIdx.x;

    // ---- main-loop weights for this k -> registers (issue LDGs early;
    //      their latency is hidden by the producer phase / spin) ----
    float W0[32], W1[8], W2[8];
    #pragma unroll
    for (int m = 0; m < 32; m++) W0[m] = w0e[m * K1V + k];
    #pragma unroll
    for (int m = 0; m < 8; m++)  W1[m] = w1o[m * K1V + k];
    #pragma unroll
    for (int m = 0; m < 8; m++)  W2[m] = w2e[m * K1V + k];

    // ================= producer phase =========================================
    if (lin < 64) {
        const int v = lin;
        // scratch inside stage[0] (rewritten later, after barriers)
        float* sxin = &stage[0][0];      // 120 floats
        float* sh   = &stage[0][128];    // 192 floats

        for (int i = t; i < 120; i += 64) sxin[i] = x[v * 120 + i];
        __syncthreads();

        // layer 0: [0:64) h0e | [64:144) h2e (o*5+c) | [144:192) h1o (o*3+c)
        for (int e = t; e < 192; e += 64) {
            float acc = 0.0f;
            if (e < 64) {
                #pragma unroll
                for (int i = 0; i < 32; i++) acc += sxin[i] * w1b0_0e[i * 64 + e];
                acc *= RS32;
            } else if (e < 144) {
                int o = (e - 64) / 5, c = (e - 64) % 5;
                #pragma unroll
                for (int i = 0; i < 8; i++) acc += sxin[80 + i * 5 + c] * w1b0_2e[i * 16 + o];
                acc *= RS8;
            } else {
                int o = (e - 144) / 3, c = (e - 144) % 3;
                #pragma unroll
                for (int i = 0; i < 16; i++) acc += sxin[32 + i * 3 + c] * w1b0_1o[i * 16 + o];
                acc *= RS16;
            }
            sh[e] = acc;
        }
        __syncthreads();

        // layer 1 -> g_x1 + x_out.
        // HID1: 0e 0:32 | 0o 32:48 (0) | 1e 48:96 (0) | 2e 96:136 | 1o 136:160 | 2o 160:180 (0)
        for (int e = t; e < 180; e += 64) {
            float acc = 0.0f;
            if (e < 32) {
                #pragma unroll
                for (int i = 0; i < 64; i++) acc += sh[i] * w1b1_0e[i * 32 + e];
                acc *= RS64;
            } else if (e >= 96 && e < 136) {
                int o = (e - 96) / 5, c = (e - 96) % 5;
                #pragma unroll
                for (int i = 0; i < 16; i++) acc += sh[64 + i * 5 + c] * w1b1_2e[i * 8 + o];
                acc *= RS16;
            } else if (e >= 136 && e < 160) {
                int o = (e - 136) / 3, c = (e - 136) % 3;
                #pragma unroll
                for (int i = 0; i < 16; i++) acc += sh[144 + i * 3 + c] * w1b1_1o[i * 8 + o];
                acc *= RS16;
            }
            g_x1[v * 180 + e] = acc;
            out[v * 180 + e] = acc;      // x_out
        }
        __threadfence();                 // make g_x1 globally visible
        __syncthreads();
        if (t == 0) atomicAdd(&g_ready, 1);
    } else if (lin == 64) {
        // ---- closest_radii (does not gate the barrier) ----
        for (int n = t; n < 512; n += 64) {
            int i = n >> 6, j = (n >> 3) & 7, kk = n & 7;
            float di = (float)i - (floorf((float)i * 0.5f) * 2.0f + 0.5f);
            float dj = (float)j - (floorf((float)j * 0.5f) * 2.0f + 0.5f);
            float dk = (float)kk - (floorf((float)kk * 0.5f) * 2.0f + 0.5f);
            float r = sqrtf(di * di + dj * dj + dk * dk);
            int best = 0; float bd = 3.4e38f;
            for (int q = 0; q < 64; q++) {
                float d = fabsf(r - (float)q * (2.0f / 63.0f));
                if (d < bd) { bd = d; best = q; }
            }
            out[RAD_OFF + n] = (float)best;
        }
    }

    // ================= barrier: wait until all 64 producer blocks arrived ====
    if (t == 0) {
        while (ld_acquire_gpu(&g_ready) < 64u) __nanosleep(64);
    }
    __syncthreads();

    // ---- stage x1 for the voxel batch (float4 loads) ----
    {
        const float4* src = (const float4*)(g_x1 + v0 * 180);
        float4* dst = (float4*)sx;
        for (int i = t; i < VB * 180 / 4; i += 64) dst[i] = src[i];
    }
    __syncthreads();

    // ================= main loop (identical to R10) ===========================
    const float S3  = 1.7320508075688772f;
    const float S15 = 3.872983346207417f;
    const float S5  = 2.23606797749979f;
    const float H3  = 0.8660254037844386f;   // sqrt(3)/2
    const float Q3  = 0.4330127018922193f;   // sqrt(3)/4
    const float SB[6] = {0.25881904510252074f, 0.7071067811865476f, 0.9659258262890683f,
                         0.9659258262890683f, 0.7071067811865476f, 0.25881904510252074f};
    const float CB[6] = {0.9659258262890683f, 0.7071067811865476f, 0.25881904510252074f,
                        -0.25881904510252074f, -0.7071067811865476f, -0.9659258262890683f};
    // alpha tables for a = 0..5 only; a+6 flips CA,SA sign; CS,C2 unchanged
    const float CA[6] = {1.f, H3, 0.5f, 0.f, -0.5f, -H3};
    const float SA[6] = {0.f, 0.5f, H3, 1.f, H3, 0.5f};
    const float CS[6] = {0.f, Q3, Q3, 0.f, -Q3, -Q3};
    const float C2[6] = {1.f, 0.5f, -0.5f, -1.f, -0.5f, 0.5f};

    const int  k0b  = blockIdx.x * 64;           // first k of this block's tile
    const bool flip = (l & 4) != 0;              // lane's beta iteration direction

    for (int iv = 0; iv < VB; iv++) {
        const int buf = iv & 1;
        const float* xv = sx + iv * 180;

        // ---- 9 SH coefficients (reads sx only) ----
        float a0 = 0.f, a1 = 0.f, a2 = 0.f, a3 = 0.f;     // 4-way ILP for c0
        #pragma unroll
        for (int m = 0; m < 32; m += 4) {
            a0 += xv[m]     * W0[m];
            a1 += xv[m + 1] * W0[m + 1];
            a2 += xv[m + 2] * W0[m + 2];
            a3 += xv[m + 3] * W0[m + 3];
        }
        float c0 = (a0 + a1) + (a2 + a3);
        c0 *= RS32;

        float c1x = 0.f, c1y = 0.f, c1z = 0.f;
        #pragma unroll
        for (int m = 0; m < 8; m++) {
            float wm = W1[m];
            c1x += xv[136 + 3 * m] * wm;
            c1y += xv[137 + 3 * m] * wm;
            c1z += xv[138 + 3 * m] * wm;
        }
        c1x *= RS8; c1y *= RS8; c1z *= RS8;

        float c2[5] = {0.f, 0.f, 0.f, 0.f, 0.f};
        #pragma unroll
        for (int m = 0; m < 8; m++) {
            float wm = W2[m];
            #pragma unroll
            for (int j = 0; j < 5; j++) c2[j] += xv[96 + 5 * m + j] * wm;
        }
        #pragma unroll
        for (int j = 0; j < 5; j++) c2[j] *= RS8;

        // ---- drain the TMA store from 2 voxels ago (same buffer) ----
        if (iv >= 2 && t == 0) {
            asm volatile("cp.async.bulk.wait_group.read 1;" ::: "memory");
        }
        __syncthreads();

        // ---- projection into stage row (thread t owns k-row t of the tile);
        //      beta-flip keeps STS.128 conflict-free; even/odd alpha symmetry ----
        float* row = &stage[buf][t * 72];
        #pragma unroll
        for (int bb = 0; bb < 6; bb++) {
            float sb = SB[bb];                        // SB[5-bb] == SB[bb]
            float cb = flip ? -CB[bb] : CB[bb];       // CB[5-bb] == -CB[bb]
            int   be = flip ? (5 - bb) : bb;          // effective beta row
            float d0 = c0 + c1z * (S3 * cb) + c2[2] * (0.5f * S5 * (3.0f * cb * cb - 1.0f));
            float d1 = c1x * (S3 * sb) + c2[3] * (S15 * sb * cb);
            float d2 = c1y * (S3 * sb) + c2[1] * (S15 * sb * cb);
            float d3 = c2[0] * (S15 * sb * sb);
            float d4 = c2[4] * (0.5f * S15 * sb * sb);

            float vals[12];
            #pragma unroll
            for (int a = 0; a < 6; a++) {
                float E = d0 + d3 * CS[a] + d4 * C2[a];
                float O = d1 * CA[a] + d2 * SA[a];
                vals[a]     = E + O;
                vals[a + 6] = E - O;
            }
            #pragma unroll
            for (int p = 0; p < 3; p++) {
                float4 r;
                r.x = vals[4 * p]; r.y = vals[4 * p + 1];
                r.z = vals[4 * p + 2]; r.w = vals[4 * p + 3];
                *(float4*)(row + be * 12 + p * 4) = r;
            }
        }
        __syncthreads();

        // ---- one async bulk store per (block, voxel): 64 rows x 72 floats ----
        if (t == 0) {
            asm volatile("fence.proxy.async.shared::cta;" ::: "memory");
            float* dst = out + XOUT_N + ((size_t)(v0 + iv) * K1V + k0b) * 72;
            unsigned int src = smem_u32(&stage[buf][0]);
            asm volatile("cp.async.bulk.global.shared::cta.bulk_group [%0], [%1], %2;"
                         :: "l"(dst), "r"(src), "r"(64 * 72 * 4) : "memory");
            asm volatile("cp.async.bulk.commit_group;" ::: "memory");
        }
    }

    // ================= epilogue: last block resets flags (graph-replayable) ===
    if (t == 0) {
        unsigned c = atomicAdd(&g_done, 1);
        if (c == (unsigned)(NBLK - 1)) {
            atomicExch(&g_ready, 0);
            atomicExch(&g_done, 0);
        }
    }
    // outstanding bulk stores complete before kernel completion is visible
}

// ---------------------------------------------------------------------------
// Launch
// ---------------------------------------------------------------------------
extern "C" void kernel_launch(void* const* d_in, const int* in_sizes, int n_in,
                              void* d_out, int out_size)
{
    const float* x        = (const float*)d_in[0];
    const float* w1b0_0e  = (const float*)d_in[1];
    const float* w1b0_1o  = (const float*)d_in[2];
    const float* w1b0_2e  = (const float*)d_in[3];
    // d_in[4..6] = w2b0_* : dead (grid0 unused)
    const float* w1b1_0e  = (const float*)d_in[7];
    // d_in[8] w1b1_0o, d_in[9] w1b1_1e : dead (input segments are zero)
    const float* w1b1_1o  = (const float*)d_in[10];
    const float* w1b1_2e  = (const float*)d_in[11];
    // d_in[12] w1b1_2o : dead
    const float* w2b1_0e  = (const float*)d_in[13];
    const float* w2b1_1o  = (const float*)d_in[14];
    const float* w2b1_2e  = (const float*)d_in[15];
    float* out = (float*)d_out;

    dim3 grid(GX, GY);
    k_all<<<grid, 64>>>(x, w1b0_0e, w1b0_1o, w1b0_2e,
                        w1b1_0e, w1b1_1o, w1b1_2e,
                        w2b1_0e, w2b1_1o, w2b1_2e, out);
}

// round 14
// speedup vs baseline: 1.0825x; 1.0825x over previous
#include <cuda_runtime.h>
#include <cstdint>
#include <math.h>

// ---------------------------------------------------------------------------
// Problem constants
// ---------------------------------------------------------------------------
#define NVOX    64          // 4*4*4 voxels (batch 1)
#define K1V     11520       // N_RADII * idim(HID1) = 64 * 180
#define XOUT_N  11520       // 64 * 180  (x_out elements)
#define GRID1_N 53084160    // 64 * 11520 * 72
#define RAD_OFF (XOUT_N + GRID1_N)

#define RS64 0.125f
#define RS32 0.17677669529663687f   // 1/sqrt(32)
#define RS16 0.25f
#define RS8  0.35355339059327373f   // 1/sqrt(8)

// voxels >= VSPLIT get L2::evict_last on their output stores (last ~93 MB,
// sized to fit the 126 MB L2 alongside weights); earlier voxels evict_first.
#define VSPLIT 36

// scratch (allocation-free rule: __device__ globals)
__device__ __align__(16) float g_x1[NVOX * 180];   // HID1 features

// ---------------------------------------------------------------------------
// Pre kernel: 64 blocks = per-voxel fused (lin0 -> lin1), block 64 = radii
// ---------------------------------------------------------------------------
__global__ void __launch_bounds__(256) k_pre(
    const float* __restrict__ x,
    const float* __restrict__ w1b0_0e,   // [32,64]
    const float* __restrict__ w1b0_1o,   // [16,16]
    const float* __restrict__ w1b0_2e,   // [8,16]
    const float* __restrict__ w1b1_0e,   // [64,32]
    const float* __restrict__ w1b1_1o,   // [16,8]
    const float* __restrict__ w1b1_2e,   // [16,8]
    float* __restrict__ out)
{
    const int t = threadIdx.x;
    const int blk = blockIdx.x;

    if (blk == 64) {
        // ---- closest_radii: fine grid (8,8,8), nearest bin of linspace(0,2,64)
        for (int n = t; n < 512; n += 256) {
            int i = n >> 6, j = (n >> 3) & 7, k = n & 7;
            float di = (float)i - (floorf((float)i * 0.5f) * 2.0f + 0.5f);
            float dj = (float)j - (floorf((float)j * 0.5f) * 2.0f + 0.5f);
            float dk = (float)k - (floorf((float)k * 0.5f) * 2.0f + 0.5f);
            float r = sqrtf(di * di + dj * dj + dk * dk);
            int best = 0; float bd = 3.4e38f;
            for (int q = 0; q < 64; q++) {
                float d = fabsf(r - (float)q * (2.0f / 63.0f));
                if (d < bd) { bd = d; best = q; }
            }
            out[RAD_OFF + n] = (float)best;
        }
        return;
    }

    const int v = blk;
    __shared__ float sxin[120];
    __shared__ float sh[192];    // [0:64) h0e | [64:144) h2e (o*5+c) | [144:192) h1o (o*3+c)

    if (t < 120) sxin[t] = x[v * 120 + t];
    __syncthreads();

    // ---- block-0 equivariant linear (only the segments HID1 uses) ----
    if (t < 192) {
        float acc = 0.0f;
        if (t < 64) {
            #pragma unroll
            for (int i = 0; i < 32; i++) acc += sxin[i] * w1b0_0e[i * 64 + t];
            acc *= RS32;
        } else if (t < 144) {
            int o = (t - 64) / 5, c = (t - 64) % 5;
            #pragma unroll
            for (int i = 0; i < 8; i++) acc += sxin[80 + i * 5 + c] * w1b0_2e[i * 16 + o];
            acc *= RS8;
        } else {
            int o = (t - 144) / 3, c = (t - 144) % 3;
            #pragma unroll
            for (int i = 0; i < 16; i++) acc += sxin[32 + i * 3 + c] * w1b0_1o[i * 16 + o];
            acc *= RS16;
        }
        sh[t] = acc;
    }
    __syncthreads();

    // ---- block-1 equivariant linear -> x1 (HID1 layout) + x_out ----
    // HID1: 0e 0:32 | 0o 32:48 (zero) | 1e 48:96 (zero) | 2e 96:136 | 1o 136:160 | 2o 160:180 (zero)
    if (t < 180) {
        float acc = 0.0f;
        if (t < 32) {
            #pragma unroll
            for (int i = 0; i < 64; i++) acc += sh[i] * w1b1_0e[i * 32 + t];
            acc *= RS64;
        } else if (t >= 96 && t < 136) {
            int o = (t - 96) / 5, c = (t - 96) % 5;
            #pragma unroll
            for (int i = 0; i < 16; i++) acc += sh[64 + i * 5 + c] * w1b1_2e[i * 8 + o];
            acc *= RS16;
        } else if (t >= 136 && t < 160) {
            int o = (t - 136) / 3, c = (t - 136) % 3;
            #pragma unroll
            for (int i = 0; i < 16; i++) acc += sh[144 + i * 3 + c] * w1b1_1o[i * 8 + o];
            acc *= RS16;
        }
        g_x1[v * 180 + t] = acc;
        out[v * 180 + t] = acc;      // x_out
    }
}

// ---------------------------------------------------------------------------
// grid1 kernel: thread = one k; 8-voxel batch; weights in registers;
// trig-immediate projection with even/odd alpha symmetry; double-buffered
// BLOCK-level staged tile (64 k-rows x 72 floats = 18432 B contiguous in
// global) flushed with one TMA bulk store per (block, voxel), with L2
// cache-policy hints: early voxels evict_first (stream through), late
// voxels evict_last (stay dirty in L2 -> never written back in-kernel).
// grid = (K1V/64, NVOX/VB), block = 64 (2 warps)
// ---------------------------------------------------------------------------
#define VB 8

__device__ __forceinline__ unsigned int smem_u32(const void* p) {
    unsigned int a;
    asm("{ .reg .u64 tmp; cvta.to.shared.u64 tmp, %1; cvt.u32.u64 %0, tmp; }"
        : "=r"(a) : "l"(p));
    return a;
}

__global__ void __launch_bounds__(64) k_grid1(
    const float* __restrict__ w0e,  // [32,K1]
    const float* __restrict__ w1o,  // [8,K1]
    const float* __restrict__ w2e,  // [8,K1]
    float* __restrict__ out)
{
    __shared__ __align__(16) float sx[VB * 180];
    __shared__ __align__(16) float stage[2][64 * 72];   // [buf][block tile] 36864 B

    const int t  = threadIdx.x;
    const int l  = t & 31;
    const int k  = blockIdx.x * 64 + t;
    const int v0 = blockIdx.y * VB;

    // ---- weights for this k -> registers ----
    float W0[32], W1[8], W2[8];
    #pragma unroll
    for (int m = 0; m < 32; m++) W0[m] = w0e[m * K1V + k];
    #pragma unroll
    for (int m = 0; m < 8; m++)  W1[m] = w1o[m * K1V + k];
    #pragma unroll
    for (int m = 0; m < 8; m++)  W2[m] = w2e[m * K1V + k];

    // ---- L2 cache policies for the output stores ----
    unsigned long long pol_first, pol_last;
    asm("createpolicy.fractional.L2::evict_first.b64 %0, 1.0;" : "=l"(pol_first));
    asm("createpolicy.fractional.L2::evict_last.b64 %0, 1.0;"  : "=l"(pol_last));

    // ---- stage x1 for the voxel batch (float4 loads) ----
    {
        const float4* src = (const float4*)(g_x1 + v0 * 180);
        float4* dst = (float4*)sx;
        for (int i = t; i < VB * 180 / 4; i += 64) dst[i] = src[i];
    }
    __syncthreads();

    // compile-time trig tables (angles are multiples of 15/30 degrees)
    const float S3  = 1.7320508075688772f;
    const float S15 = 3.872983346207417f;
    const float S5  = 2.23606797749979f;
    const float H3  = 0.8660254037844386f;   // sqrt(3)/2
    const float Q3  = 0.4330127018922193f;   // sqrt(3)/4
    const float SB[6] = {0.25881904510252074f, 0.7071067811865476f, 0.9659258262890683f,
                         0.9659258262890683f, 0.7071067811865476f, 0.25881904510252074f};
    const float CB[6] = {0.9659258262890683f, 0.7071067811865476f, 0.25881904510252074f,
                        -0.25881904510252074f, -0.7071067811865476f, -0.9659258262890683f};
    // alpha tables for a = 0..5 only; a+6 flips CA,SA sign; CS,C2 unchanged
    const float CA[6] = {1.f, H3, 0.5f, 0.f, -0.5f, -H3};
    const float SA[6] = {0.f, 0.5f, H3, 1.f, H3, 0.5f};
    const float CS[6] = {0.f, Q3, Q3, 0.f, -Q3, -Q3};
    const float C2[6] = {1.f, 0.5f, -0.5f, -1.f, -0.5f, 0.5f};

    const int  k0b  = blockIdx.x * 64;           // first k of this block's tile
    const bool flip = (l & 4) != 0;              // lane's beta iteration direction

    for (int iv = 0; iv < VB; iv++) {
        const int buf = iv & 1;
        const float* xv = sx + iv * 180;

        // ---- 9 SH coefficients for this (v, k) — reads sx only ----
        float a0 = 0.f, a1 = 0.f, a2 = 0.f, a3 = 0.f;     // 4-way ILP for c0
        #pragma unroll
        for (int m = 0; m < 32; m += 4) {
            a0 += xv[m]     * W0[m];
            a1 += xv[m + 1] * W0[m + 1];
            a2 += xv[m + 2] * W0[m + 2];
            a3 += xv[m + 3] * W0[m + 3];
        }
        float c0 = (a0 + a1) + (a2 + a3);
        c0 *= RS32;

        float c1x = 0.f, c1y = 0.f, c1z = 0.f;
        #pragma unroll
        for (int m = 0; m < 8; m++) {
            float wm = W1[m];
            c1x += xv[136 + 3 * m] * wm;
            c1y += xv[137 + 3 * m] * wm;
            c1z += xv[138 + 3 * m] * wm;
        }
        c1x *= RS8; c1y *= RS8; c1z *= RS8;

        float c2[5] = {0.f, 0.f, 0.f, 0.f, 0.f};
        #pragma unroll
        for (int m = 0; m < 8; m++) {
            float wm = W2[m];
            #pragma unroll
            for (int j = 0; j < 5; j++) c2[j] += xv[96 + 5 * m + j] * wm;
        }
        #pragma unroll
        for (int j = 0; j < 5; j++) c2[j] *= RS8;

        // ---- drain the TMA store from 2 voxels ago (same buffer) ----
        if (iv >= 2 && t == 0) {
            asm volatile("cp.async.bulk.wait_group.read 1;" ::: "memory");
        }
        __syncthreads();

        // ---- projection into stage row (thread t owns k-row t of the tile);
        //      beta-flip keeps STS.128 conflict-free; even/odd alpha symmetry ----
        float* row = &stage[buf][t * 72];
        #pragma unroll
        for (int bb = 0; bb < 6; bb++) {
            float sb = SB[bb];                        // SB[5-bb] == SB[bb]
            float cb = flip ? -CB[bb] : CB[bb];       // CB[5-bb] == -CB[bb]
            int   be = flip ? (5 - bb) : bb;          // effective beta row
            float d0 = c0 + c1z * (S3 * cb) + c2[2] * (0.5f * S5 * (3.0f * cb * cb - 1.0f));
            float d1 = c1x * (S3 * sb) + c2[3] * (S15 * sb * cb);
            float d2 = c1y * (S3 * sb) + c2[1] * (S15 * sb * cb);
            float d3 = c2[0] * (S15 * sb * sb);
            float d4 = c2[4] * (0.5f * S15 * sb * sb);

            float vals[12];
            #pragma unroll
            for (int a = 0; a < 6; a++) {
                float E = d0 + d3 * CS[a] + d4 * C2[a];
                float O = d1 * CA[a] + d2 * SA[a];
                vals[a]     = E + O;
                vals[a + 6] = E - O;
            }
            #pragma unroll
            for (int p = 0; p < 3; p++) {
                float4 r;
                r.x = vals[4 * p]; r.y = vals[4 * p + 1];
                r.z = vals[4 * p + 2]; r.w = vals[4 * p + 3];
                *(float4*)(row + be * 12 + p * 4) = r;
            }
        }
        __syncthreads();

        // ---- one async bulk store per (block, voxel): 64 rows x 72 floats.
        //      Late voxels (>= VSPLIT) evict_last -> stay dirty in L2. ----
        if (t == 0) {
            asm volatile("fence.proxy.async.shared::cta;" ::: "memory");
            float* dst = out + XOUT_N + ((size_t)(v0 + iv) * K1V + k0b) * 72;
            unsigned int src = smem_u32(&stage[buf][0]);
            unsigned long long pol = (v0 + iv >= VSPLIT) ? pol_last : pol_first;
            asm volatile(
                "cp.async.bulk.global.shared::cta.bulk_group.L2::cache_hint [%0], [%1], %2, %3;"
                :: "l"(dst), "r"(src), "r"(64 * 72 * 4), "l"(pol) : "memory");
            asm volatile("cp.async.bulk.commit_group;" ::: "memory");
        }
    }
    // outstanding bulk stores complete before kernel completion is visible
}

// ---------------------------------------------------------------------------
// Launch
// ---------------------------------------------------------------------------
extern "C" void kernel_launch(void* const* d_in, const int* in_sizes, int n_in,
                              void* d_out, int out_size)
{
    const float* x        = (const float*)d_in[0];
    const float* w1b0_0e  = (const float*)d_in[1];
    const float* w1b0_1o  = (const float*)d_in[2];
    const float* w1b0_2e  = (const float*)d_in[3];
    // d_in[4..6] = w2b0_* : dead (grid0 unused)
    const float* w1b1_0e  = (const float*)d_in[7];
    // d_in[8] w1b1_0o, d_in[9] w1b1_1e : dead (input segments are zero)
    const float* w1b1_1o  = (const float*)d_in[10];
    const float* w1b1_2e  = (const float*)d_in[11];
    // d_in[12] w1b1_2o : dead
    const float* w2b1_0e  = (const float*)d_in[13];
    const float* w2b1_1o  = (const float*)d_in[14];
    const float* w2b1_2e  = (const float*)d_in[15];
    float* out = (float*)d_out;

    k_pre<<<65, 256>>>(x, w1b0_0e, w1b0_1o, w1b0_2e,
                       w1b1_0e, w1b1_1o, w1b1_2e, out);

    dim3 grid(K1V / 64, NVOX / VB);
    k_grid1<<<grid, 64>>>(w2b1_0e, w2b1_1o, w2b1_2e, out);
}